// round 14
// baseline (speedup 1.0000x reference)
#include <cuda_runtime.h>
#include <cuda_bf16.h>
#include <cstdint>

#define S_LEN 128
#define B_SZ  64
#define V_SZ  32000
#define E_SZ  32
#define H_SZ  16
#define NROWS (S_LEN * B_SZ)   // 8192

#define MT     128             // rows per tile (8 warps x 16 rows)
#define NMT    (NROWS / MT)    // 64 tiles
#define VSPLIT 16
#define VR     (V_SZ / VSPLIT) // 2000 cols per chunk
#define NG     (VR / 16)       // 125 col-groups
#define NWT2   (V_SZ * H_SZ / 2)
#define NPART  4               // sum-job parts per chunk
#define NJOB   (NMT * VSPLIT * NPART)  // 4096

#define LOG2E 1.4426950408889634f
#define LN2   0.6931471805599453f

// -------- device scratch (allocation-free rule) --------------------------------
__device__ float    g_xin[NROWS * H_SZ];
__device__ float    g_h[NROWS * H_SZ];
__device__ uint32_t g_wt2[NWT2];                 // Wo in MMA-B-fragment layout
__device__ float    g_ps2[NROWS * VSPLIT * NPART]; // partial sums [row][chunk*4+part]
__device__ int          g_ctr;                   // job counter
__device__ volatile int g_tdone[NMT];            // per-tile completed jobs (of 64)

// -------- helpers ---------------------------------------------------------------
__device__ __forceinline__ uint32_t packbf(float lo, float hi) {
    __nv_bfloat162 p = __floats2bfloat162_rn(lo, hi);
    return *reinterpret_cast<uint32_t*>(&p);
}
__device__ __forceinline__ float ex2(float x) {
    float r;
    asm("ex2.approx.f32 %0, %1;" : "=f"(r) : "f"(x));
    return r;
}
__device__ __forceinline__ void mma16816(float d[4], const uint32_t a[4],
                                         uint32_t b0, uint32_t b1) {
    float z = 0.f;
    asm volatile(
        "mma.sync.aligned.m16n8k16.row.col.f32.bf16.bf16.f32 "
        "{%0,%1,%2,%3}, {%4,%5,%6,%7}, {%8,%9}, {%10,%11,%12,%13};"
        : "=f"(d[0]), "=f"(d[1]), "=f"(d[2]), "=f"(d[3])
        : "r"(a[0]), "r"(a[1]), "r"(a[2]), "r"(a[3]),
          "r"(b0), "r"(b1),
          "f"(z), "f"(z), "f"(z), "f"(z));
}
// Build the loop-invariant A fragment (rows wr0.., log2e-scaled) for a tile.
__device__ __forceinline__ void build_a(uint32_t a[4], int wr0, int rA, int kc) {
    const float* hA = g_h + (long)(wr0 + rA) * H_SZ;
    const float* hB = g_h + (long)(wr0 + rA + 8) * H_SZ;
    a[0] = packbf(LOG2E * hA[kc],     LOG2E * hA[kc + 1]);
    a[1] = packbf(LOG2E * hB[kc],     LOG2E * hB[kc + 1]);
    a[2] = packbf(LOG2E * hA[kc + 8], LOG2E * hA[kc + 9]);
    a[3] = packbf(LOG2E * hB[kc + 8], LOG2E * hB[kc + 9]);
}

// -------- K0: xin = lookup[idx] @ Wx  (+ counter reset for this launch) ---------
__global__ void k_embed(const int* __restrict__ idx,
                        const float* __restrict__ lookup,
                        const float* __restrict__ wx) {
    if (blockIdx.x == 0) {
        if (threadIdx.x < NMT) g_tdone[threadIdx.x] = 0;
        if (threadIdx.x == NMT) g_ctr = 0;
    }
    int t = blockIdx.x * blockDim.x + threadIdx.x;  // 32768 threads
    int row = t >> 2, j0 = (t & 3) * 4;
    const float4* L4 = reinterpret_cast<const float4*>(lookup + (long)idx[row] * E_SZ);
    float4 acc = make_float4(0.f, 0.f, 0.f, 0.f);
#pragma unroll
    for (int e4 = 0; e4 < E_SZ / 4; e4++) {
        float4 lv = L4[e4];
#pragma unroll
        for (int c = 0; c < 4; c++) {
            float le = (c == 0) ? lv.x : (c == 1) ? lv.y : (c == 2) ? lv.z : lv.w;
            float4 wv = *reinterpret_cast<const float4*>(wx + (e4 * 4 + c) * H_SZ + j0);
            acc.x += le * wv.x; acc.y += le * wv.y;
            acc.z += le * wv.z; acc.w += le * wv.w;
        }
    }
    *reinterpret_cast<float4*>(g_xin + (long)row * H_SZ + j0) = acc;
}

// -------- K_prep: fused recurrence (blocks 0..31) + Wo repack (blocks 32..95) ---
__global__ void k_prep(const float* __restrict__ wh,
                       const float* __restrict__ h0,
                       const float* __restrict__ wo) {
    int blk = blockIdx.x;
    if (blk < 32) {
        int tid = threadIdx.x;
        if (tid >= 32) return;
        int half = tid >> 4;
        int j    = tid & 15;
        int bb   = blk * 2 + half;
        int base = bb * H_SZ + j;
        int src0 = half << 4;

        float whr[H_SZ];
#pragma unroll
        for (int k = 0; k < H_SZ; k++) whr[k] = wh[k * H_SZ + j];

        float h   = h0[base];
        float xin = g_xin[base];
        for (int s = 0; s < S_LEN; s++) {
            float nxt = (s + 1 < S_LEN) ? g_xin[(s + 1) * (B_SZ * H_SZ) + base] : 0.f;
            float acc = xin;
#pragma unroll
            for (int k = 0; k < H_SZ; k++) {
                float hk = __shfl_sync(0xffffffffu, h, src0 | k);
                acc += hk * whr[k];
            }
            float e = ex2(acc * (2.0f * LOG2E));
            h = __fdividef(e - 1.0f, e + 1.0f);
            g_h[s * (B_SZ * H_SZ) + base] = h;
            xin = nxt;
        }
    } else {
        int t0 = ((blk - 32) * 256 + threadIdx.x) * 16;
        if (t0 >= NWT2) return;
        uint32_t v[16];
#pragma unroll
        for (int i = 0; i < 16; i++) {
            int t = t0 + i;
            int g = t >> 7, rem = t & 127;
            int lane = rem >> 2, r = rem & 3;
            int tc   = lane >> 2;
            int tile = r >> 1;
            int col  = g * 16 + 2 * tc - (tc & 1) + 2 * tile;
            int k0   = (lane & 3) * 2 + (r & 1) * 8;
            v[i] = packbf(wo[k0 * V_SZ + col], wo[(k0 + 1) * V_SZ + col]);
        }
        uint4* dst = reinterpret_cast<uint4*>(g_wt2 + t0);
#pragma unroll
        for (int i = 0; i < 4; i++)
            dst[i] = make_uint4(v[4 * i], v[4 * i + 1], v[4 * i + 2], v[4 * i + 3]);
    }
}

// -------- K2: work-stealing pass0 (tile-ordered sum jobs) + owner pass1 ---------
// grid = 1024. Sum jobs (4096, tile-ordered) are grabbed via g_ctr by ALL blocks;
// a block defects to its own tile's store stream as soon as that tile's 64 jobs
// are done => stores (DRAM-bound) start after ~1 job round and hide the rest of
// pass0. Partials are deterministic (fixed group ranges, fixed combine order).
__global__ __launch_bounds__(256)
void k2f(float* __restrict__ out) {
    __shared__ int sj;
    int blk  = blockIdx.x;
    int Tm   = blk >> 4;             // owned tile
    int bxm  = blk & 15;             // owned chunk
    int tid  = threadIdx.x;
    int w    = tid >> 5;
    int lane = tid & 31;
    int lq   = lane & 3;
    int rA   = lane >> 2;
    int kc   = lq * 2;

    // ---- pass 0: grab tile-ordered sum jobs until own tile is ready ----
    for (;;) {
        __syncthreads();
        if (tid == 0) {
            int j = -1;
            if (g_tdone[Tm] < 64) {
                j = atomicAdd(&g_ctr, 1);
                if (j >= NJOB) j = -1;
            }
            sj = j;
        }
        __syncthreads();
        int j = sj;
        if (j < 0) break;

        int cj  = j >> 2;            // chunk id, tile-ordered
        int p   = j & 3;
        int Tj  = cj >> 4;
        int bxj = cj & 15;
        int wr0 = Tj * MT + w * 16;
        uint32_t a[4];
        build_a(a, wr0, rA, kc);
        const uint4* bptr = reinterpret_cast<const uint4*>(g_wt2)
                            + (long)bxj * NG * 32 + lane;
        int g0 = p * 32;
        int g1 = (g0 + 32 < NG) ? g0 + 32 : NG;

        float psA = 0.f, psB = 0.f;
#pragma unroll 4
        for (int g = g0; g < g1; g++) {
            uint4 b = bptr[(long)g * 32];
            float d0[4], d1[4];
            mma16816(d0, a, b.x, b.y);
            mma16816(d1, a, b.z, b.w);
            psA += ex2(d0[0]) + ex2(d0[1]) + ex2(d1[0]) + ex2(d1[1]);
            psB += ex2(d0[2]) + ex2(d0[3]) + ex2(d1[2]) + ex2(d1[3]);
        }
        psA += __shfl_xor_sync(0xffffffffu, psA, 1);
        psA += __shfl_xor_sync(0xffffffffu, psA, 2);
        psB += __shfl_xor_sync(0xffffffffu, psB, 1);
        psB += __shfl_xor_sync(0xffffffffu, psB, 2);
        if (lq == 0) {
            g_ps2[(long)(wr0 + rA) * (VSPLIT * NPART) + bxj * 4 + p]     = psA;
            g_ps2[(long)(wr0 + rA + 8) * (VSPLIT * NPART) + bxj * 4 + p] = psB;
        }
        __threadfence();
        __syncthreads();
        if (tid == 0) atomicAdd((int*)&g_tdone[Tj], 1);
    }

    // ---- wait: own tile's 64 sum jobs complete ----
    if (lane == 0) {
        while (g_tdone[Tm] < 64) __nanosleep(64);
    }
    __syncthreads();
    __threadfence();

    int wr0 = Tm * MT + w * 16;

    // lse per row: combine 64 partials in FIXED order (deterministic)
    float lseA, lseB;
    {
        const float4* pp = reinterpret_cast<const float4*>(
            g_ps2 + (long)(wr0 + rA) * (VSPLIT * NPART));
        const float4* qq = reinterpret_cast<const float4*>(
            g_ps2 + (long)(wr0 + rA + 8) * (VSPLIT * NPART));
        float sa = 0.f, sb = 0.f;
#pragma unroll
        for (int i = 0; i < VSPLIT * NPART / 4; i++) {
            float4 pv = pp[i], qv = qq[i];
            sa += (pv.x + pv.y) + (pv.z + pv.w);
            sb += (qv.x + qv.y) + (qv.z + qv.w);
        }
        lseA = __logf(sa);
        lseB = __logf(sb);
    }

    // ---- pass 1: recompute logits for own chunk, store logit*ln2 - lse ----
    uint32_t a[4];
    build_a(a, wr0, rA, kc);
    const uint4* bptr = reinterpret_cast<const uint4*>(g_wt2)
                        + (long)bxm * NG * 32 + lane;
    long orowA = (long)(wr0 + rA) * V_SZ + bxm * VR + 4 * lq;
    long orowB = orowA + 8L * V_SZ;

#pragma unroll 5
    for (int g = 0; g < NG; g++) {
        uint4 b = bptr[(long)g * 32];
        float d0[4], d1[4];
        mma16816(d0, a, b.x, b.y);
        mma16816(d1, a, b.z, b.w);
        float4 vA = make_float4(fmaf(d0[0], LN2, -lseA), fmaf(d0[1], LN2, -lseA),
                                fmaf(d1[0], LN2, -lseA), fmaf(d1[1], LN2, -lseA));
        float4 vB = make_float4(fmaf(d0[2], LN2, -lseB), fmaf(d0[3], LN2, -lseB),
                                fmaf(d1[2], LN2, -lseB), fmaf(d1[3], LN2, -lseB));
        *reinterpret_cast<float4*>(out + orowA + g * 16) = vA;
        *reinterpret_cast<float4*>(out + orowB + g * 16) = vB;
    }
}

// -------- launch ----------------------------------------------------------------
extern "C" void kernel_launch(void* const* d_in, const int* in_sizes, int n_in,
                              void* d_out, int out_size) {
    const int*   input_batch = (const int*)d_in[0];
    const float* lookup      = (const float*)d_in[1];
    const float* weight_x    = (const float*)d_in[2];
    const float* weight_h    = (const float*)d_in[3];
    const float* weight_o    = (const float*)d_in[4];
    const float* h0          = (const float*)d_in[5];
    float*       out         = (float*)d_out;

    k_embed<<<(NROWS * H_SZ / 4) / 256, 256>>>(input_batch, lookup, weight_x);
    k_prep<<<96, 256>>>(weight_h, h0, weight_o);
    k2f<<<VSPLIT * NMT, 256>>>(out);
}

// round 16
// speedup vs baseline: 1.0663x; 1.0663x over previous
#include <cuda_runtime.h>
#include <cuda_bf16.h>
#include <cstdint>

#define S_LEN 128
#define B_SZ  64
#define V_SZ  32000
#define E_SZ  32
#define H_SZ  16
#define NROWS (S_LEN * B_SZ)   // 8192

#define MT     128             // rows per tile (8 warps x 16 rows)
#define NMT    (NROWS / MT)    // 64 tiles
#define VSPLIT 16
#define VR     (V_SZ / VSPLIT) // 2000 cols per chunk
#define NG     (VR / 16)       // 125 col-groups
#define GSPLIT 63              // phase group split: [0,63) / [63,125)
#define NWT2   (V_SZ * H_SZ / 2)
#define PRIO   32              // priority tiles: 0..31

#define LOG2E 1.4426950408889634f
#define LN2   0.6931471805599453f

// -------- device scratch (allocation-free rule) --------------------------------
__device__ float    g_xin[NROWS * H_SZ];
__device__ float    g_h[NROWS * H_SZ];
__device__ uint32_t g_wt2[NWT2];              // Wo in MMA-B-fragment layout
__device__ float    g_ps2[NROWS * 32];        // partials [row][chunk*2+half]
__device__ volatile int g_tdone[NMT];         // per-tile partial count (target 32)

// -------- helpers ---------------------------------------------------------------
__device__ __forceinline__ uint32_t packbf(float lo, float hi) {
    __nv_bfloat162 p = __floats2bfloat162_rn(lo, hi);
    return *reinterpret_cast<uint32_t*>(&p);
}
__device__ __forceinline__ float ex2(float x) {
    float r;
    asm("ex2.approx.f32 %0, %1;" : "=f"(r) : "f"(x));
    return r;
}
__device__ __forceinline__ void mma16816(float d[4], const uint32_t a[4],
                                         uint32_t b0, uint32_t b1) {
    float z = 0.f;
    asm volatile(
        "mma.sync.aligned.m16n8k16.row.col.f32.bf16.bf16.f32 "
        "{%0,%1,%2,%3}, {%4,%5,%6,%7}, {%8,%9}, {%10,%11,%12,%13};"
        : "=f"(d[0]), "=f"(d[1]), "=f"(d[2]), "=f"(d[3])
        : "r"(a[0]), "r"(a[1]), "r"(a[2]), "r"(a[3]),
          "r"(b0), "r"(b1),
          "f"(z), "f"(z), "f"(z), "f"(z));
}
__device__ __forceinline__ void build_a(uint32_t a[4], int wr0, int rA, int kc) {
    const float* hA = g_h + (long)(wr0 + rA) * H_SZ;
    const float* hB = g_h + (long)(wr0 + rA + 8) * H_SZ;
    a[0] = packbf(LOG2E * hA[kc],     LOG2E * hA[kc + 1]);
    a[1] = packbf(LOG2E * hB[kc],     LOG2E * hB[kc + 1]);
    a[2] = packbf(LOG2E * hA[kc + 8], LOG2E * hA[kc + 9]);
    a[3] = packbf(LOG2E * hB[kc + 8], LOG2E * hB[kc + 9]);
}
// Sum-of-exp over groups [g0,g1) of chunk bx for tile rows; warp-reduced.
__device__ __forceinline__ void sum_exp(const uint32_t a[4], int bx, int g0, int g1,
                                        int lane, float& outA, float& outB) {
    const uint4* bptr = reinterpret_cast<const uint4*>(g_wt2) + (long)bx * NG * 32 + lane;
    float psA = 0.f, psB = 0.f;
#pragma unroll 4
    for (int g = g0; g < g1; g++) {
        uint4 b = bptr[(long)g * 32];
        float d0[4], d1[4];
        mma16816(d0, a, b.x, b.y);
        mma16816(d1, a, b.z, b.w);
        psA += ex2(d0[0]) + ex2(d0[1]) + ex2(d1[0]) + ex2(d1[1]);
        psB += ex2(d0[2]) + ex2(d0[3]) + ex2(d1[2]) + ex2(d1[3]);
    }
    psA += __shfl_xor_sync(0xffffffffu, psA, 1);
    psA += __shfl_xor_sync(0xffffffffu, psA, 2);
    psB += __shfl_xor_sync(0xffffffffu, psB, 1);
    psB += __shfl_xor_sync(0xffffffffu, psB, 2);
    outA = psA;
    outB = psB;
}

// -------- K1: embed (blocks 0..127) + Wo repack (blocks 128..191), independent --
__global__ void k_pre(const int* __restrict__ idx,
                      const float* __restrict__ lookup,
                      const float* __restrict__ wx,
                      const float* __restrict__ wo) {
    int blk = blockIdx.x;
    if (blk == 0 && threadIdx.x < NMT) g_tdone[threadIdx.x] = 0;
    if (blk < 128) {
        int t = blk * blockDim.x + threadIdx.x;  // 32768 threads
        int row = t >> 2, j0 = (t & 3) * 4;
        const float4* L4 = reinterpret_cast<const float4*>(lookup + (long)idx[row] * E_SZ);
        float4 acc = make_float4(0.f, 0.f, 0.f, 0.f);
#pragma unroll
        for (int e4 = 0; e4 < E_SZ / 4; e4++) {
            float4 lv = L4[e4];
#pragma unroll
            for (int c = 0; c < 4; c++) {
                float le = (c == 0) ? lv.x : (c == 1) ? lv.y : (c == 2) ? lv.z : lv.w;
                float4 wv = *reinterpret_cast<const float4*>(wx + (e4 * 4 + c) * H_SZ + j0);
                acc.x += le * wv.x; acc.y += le * wv.y;
                acc.z += le * wv.z; acc.w += le * wv.w;
            }
        }
        *reinterpret_cast<float4*>(g_xin + (long)row * H_SZ + j0) = acc;
    } else {
        int t0 = ((blk - 128) * 256 + threadIdx.x) * 16;
        if (t0 >= NWT2) return;
        uint32_t v[16];
#pragma unroll
        for (int i = 0; i < 16; i++) {
            int t = t0 + i;
            int g = t >> 7, rem = t & 127;
            int lane = rem >> 2, r = rem & 3;
            int tc   = lane >> 2;
            int tile = r >> 1;
            int col  = g * 16 + 2 * tc - (tc & 1) + 2 * tile;
            int k0   = (lane & 3) * 2 + (r & 1) * 8;
            v[i] = packbf(wo[k0 * V_SZ + col], wo[(k0 + 1) * V_SZ + col]);
        }
        uint4* dst = reinterpret_cast<uint4*>(g_wt2 + t0);
#pragma unroll
        for (int i = 0; i < 4; i++)
            dst[i] = make_uint4(v[4 * i], v[4 * i + 1], v[4 * i + 2], v[4 * i + 3]);
    }
}

// -------- K2: sequential Elman recurrence (32 blocks x 32 threads) --------------
__global__ void k_recur(const float* __restrict__ wh, const float* __restrict__ h0) {
    int tid = threadIdx.x;
    int half = tid >> 4;
    int j    = tid & 15;
    int bb   = blockIdx.x * 2 + half;
    int base = bb * H_SZ + j;
    int src0 = half << 4;

    float whr[H_SZ];
#pragma unroll
    for (int k = 0; k < H_SZ; k++) whr[k] = wh[k * H_SZ + j];

    float h   = h0[base];
    float xin = g_xin[base];
    for (int s = 0; s < S_LEN; s++) {
        float nxt = (s + 1 < S_LEN) ? g_xin[(s + 1) * (B_SZ * H_SZ) + base] : 0.f;
        float acc = xin;
#pragma unroll
        for (int k = 0; k < H_SZ; k++) {
            float hk = __shfl_sync(0xffffffffu, h, src0 | k);
            acc += hk * whr[k];
        }
        float e = ex2(acc * (2.0f * LOG2E));
        h = __fdividef(e - 1.0f, e + 1.0f);
        g_h[s * (B_SZ * H_SZ) + base] = h;
        xin = nxt;
    }
}

// -------- K3: static 2-phase sums + stores --------------------------------------
// Phase A (ALL 1024 blocks): sum-partials for priority tiles 0..31
//   block b -> chunk cj=b>>1 (tile cj>>4), half pA=b&1. ~27us at full grid.
// Phase B: blocks owning tiles 32..63 compute their own chunk's two halves.
// Priority owners hit the gate at ~27us and stream stores (DRAM-bound) while
// phase B's exp work proceeds on the other half of the warps.
__global__ __launch_bounds__(256)
void k2f(float* __restrict__ out) {
    int blk  = blockIdx.x;
    int Tm   = blk >> 4;             // owned tile
    int bxm  = blk & 15;             // owned chunk
    int tid  = threadIdx.x;
    int w    = tid >> 5;
    int lane = tid & 31;
    int lq   = lane & 3;
    int rA   = lane >> 2;
    int kc   = lq * 2;

    // ---- Phase A: priority-region sum job (static) ----
    {
        int cj  = blk >> 1;          // 0..511 -> tiles 0..31
        int pA  = blk & 1;
        int Tj  = cj >> 4;
        int bxj = cj & 15;
        int wr0 = Tj * MT + w * 16;
        uint32_t a[4];
        build_a(a, wr0, rA, kc);
        float psA, psB;
        sum_exp(a, bxj, pA ? GSPLIT : 0, pA ? NG : GSPLIT, lane, psA, psB);
        if (lq == 0) {
            g_ps2[(long)(wr0 + rA) * 32 + bxj * 2 + pA]     = psA;
            g_ps2[(long)(wr0 + rA + 8) * 32 + bxj * 2 + pA] = psB;
        }
        __threadfence();
        __syncthreads();
        if (tid == 0) atomicAdd((int*)&g_tdone[Tj], 1);
    }

    int wr0 = Tm * MT + w * 16;
    uint32_t a[4];
    build_a(a, wr0, rA, kc);

    // ---- Phase B: non-priority owners compute their own chunk's sums ----
    if (Tm >= PRIO) {
        float psA0, psB0, psA1, psB1;
        sum_exp(a, bxm, 0, GSPLIT, lane, psA0, psB0);
        sum_exp(a, bxm, GSPLIT, NG, lane, psA1, psB1);
        if (lq == 0) {
            g_ps2[(long)(wr0 + rA) * 32 + bxm * 2 + 0]     = psA0;
            g_ps2[(long)(wr0 + rA) * 32 + bxm * 2 + 1]     = psA1;
            g_ps2[(long)(wr0 + rA + 8) * 32 + bxm * 2 + 0] = psB0;
            g_ps2[(long)(wr0 + rA + 8) * 32 + bxm * 2 + 1] = psB1;
        }
        __threadfence();
        __syncthreads();
        if (tid == 0) atomicAdd((int*)&g_tdone[Tm], 2);
    }

    // ---- gate: own tile's 32 partials present ----
    if (lane == 0) {
        while (g_tdone[Tm] < 32) __nanosleep(64);
    }
    __syncthreads();
    __threadfence();

    // lse per row: combine 32 partials in FIXED order (deterministic)
    float lseA, lseB;
    {
        const float4* pp = reinterpret_cast<const float4*>(g_ps2 + (long)(wr0 + rA) * 32);
        const float4* qq = reinterpret_cast<const float4*>(g_ps2 + (long)(wr0 + rA + 8) * 32);
        float sa = 0.f, sb = 0.f;
#pragma unroll
        for (int i = 0; i < 8; i++) {
            float4 pv = pp[i], qv = qq[i];
            sa += (pv.x + pv.y) + (pv.z + pv.w);
            sb += (qv.x + qv.y) + (qv.z + qv.w);
        }
        lseA = __logf(sa);
        lseB = __logf(sb);
    }

    // ---- stores: own chunk, logit*ln2 - lse ----
    const uint4* bptr = reinterpret_cast<const uint4*>(g_wt2) + (long)bxm * NG * 32 + lane;
    long orowA = (long)(wr0 + rA) * V_SZ + bxm * VR + 4 * lq;
    long orowB = orowA + 8L * V_SZ;

#pragma unroll 5
    for (int g = 0; g < NG; g++) {
        uint4 b = bptr[(long)g * 32];
        float d0[4], d1[4];
        mma16816(d0, a, b.x, b.y);
        mma16816(d1, a, b.z, b.w);
        float4 vA = make_float4(fmaf(d0[0], LN2, -lseA), fmaf(d0[1], LN2, -lseA),
                                fmaf(d1[0], LN2, -lseA), fmaf(d1[1], LN2, -lseA));
        float4 vB = make_float4(fmaf(d0[2], LN2, -lseB), fmaf(d0[3], LN2, -lseB),
                                fmaf(d1[2], LN2, -lseB), fmaf(d1[3], LN2, -lseB));
        *reinterpret_cast<float4*>(out + orowA + g * 16) = vA;
        *reinterpret_cast<float4*>(out + orowB + g * 16) = vB;
    }
}

// -------- launch ----------------------------------------------------------------
extern "C" void kernel_launch(void* const* d_in, const int* in_sizes, int n_in,
                              void* d_out, int out_size) {
    const int*   input_batch = (const int*)d_in[0];
    const float* lookup      = (const float*)d_in[1];
    const float* weight_x    = (const float*)d_in[2];
    const float* weight_h    = (const float*)d_in[3];
    const float* weight_o    = (const float*)d_in[4];
    const float* h0          = (const float*)d_in[5];
    float*       out         = (float*)d_out;

    k_pre<<<192, 256>>>(input_batch, lookup, weight_x, weight_o);
    k_recur<<<32, 32>>>(weight_h, h0);
    k2f<<<VSPLIT * NMT, 256>>>(out);
}